// round 16
// baseline (speedup 1.0000x reference)
#include <cuda_runtime.h>
#include <cuda_bf16.h>

// Problem constants (fixed by the dataset)
#define Bsz   32768
#define INF   784
#define Hdim  128
#define OUTD  10
#define NSTEP 25

typedef unsigned long long u64;

// -------- packed f32x2 helpers (Blackwell dual-fp32 pipe) --------
__device__ __forceinline__ u64 fma2(u64 a, u64 b, u64 c) {
    u64 d;
    asm("fma.rn.f32x2 %0, %1, %2, %3;" : "=l"(d) : "l"(a), "l"(b), "l"(c));
    return d;
}
__device__ __forceinline__ u64 pack2(float x, float y) {
    u64 d;
    asm("mov.b64 %0, {%1, %2};" : "=l"(d) : "f"(x), "f"(y));
    return d;
}
__device__ __forceinline__ float2 unpack2(u64 a) {
    float2 r;
    asm("mov.b64 {%0, %1}, %2;" : "=f"(r.x), "=f"(r.y) : "l"(a));
    return r;
}

// -------- device scratch (no allocation allowed) --------
__device__ float    g_cur1[(size_t)Bsz * Hdim];              // 16 MB
__device__ unsigned g_spk[(size_t)NSTEP * Bsz * 4];          // 13.1 MB spike bitmasks
__device__ u64      g_cur2[(size_t)NSTEP * Bsz * 2 * 3];     // 39.3 MB cur2 (packed pairs)

// ============================================================
// gemm1: UNCHANGED (R15). At the dual-fp32 FMA roofline (~174us):
// fma pipe counter 47.6% == one FFMA2 per 2cyc == saturated.
// ============================================================
__global__ __launch_bounds__(256, 2) void gemm1_kernel(const float* __restrict__ x,
                                                       const float* __restrict__ W1g,
                                                       const float* __restrict__ b1) {
    __shared__ __align__(16) float2 Asd[2][16][130];
    __shared__ __align__(16) float  Bs[2][16][132];
    __shared__ float  b1s[128];

    const int tid = threadIdx.x;
    const int bm = blockIdx.x * 128;

    if (tid < 128) b1s[tid] = b1[tid];

    const int arow = tid >> 2;
    const int acg  = (tid & 3) * 4;
    const int sk  = tid & 15;
    const int sc0 = tid >> 4;

    const int tx = tid & 15;
    const int ty = tid >> 4;

    u64 cp[8][4];
#pragma unroll
    for (int rr = 0; rr < 8; rr++)
#pragma unroll
        for (int j = 0; j < 4; j++) cp[rr][j] = 0ull;

    float4 a0 = *(const float4*)(x + (size_t)(bm + arow) * INF + acg);
    float4 a1 = *(const float4*)(x + (size_t)(bm + arow + 64) * INF + acg);
    float bpre[8];
#pragma unroll
    for (int p = 0; p < 8; p++)
        bpre[p] = W1g[(size_t)(sc0 + 16 * p) * INF + sk];

    {
        float2 (*As)[130] = Asd[0];
        float  (*Bb)[132] = Bs[0];
        As[acg + 0][arow] = make_float2(a0.x, a0.x);
        As[acg + 1][arow] = make_float2(a0.y, a0.y);
        As[acg + 2][arow] = make_float2(a0.z, a0.z);
        As[acg + 3][arow] = make_float2(a0.w, a0.w);
        As[acg + 0][arow + 64] = make_float2(a1.x, a1.x);
        As[acg + 1][arow + 64] = make_float2(a1.y, a1.y);
        As[acg + 2][arow + 64] = make_float2(a1.z, a1.z);
        As[acg + 3][arow + 64] = make_float2(a1.w, a1.w);
#pragma unroll
        for (int p = 0; p < 8; p++)
            Bb[sk][sc0 + 16 * p] = bpre[p];
    }
    __syncthreads();

    const int KITER = INF / 16;  // 49
    int cb = 0;
    for (int t = 0; t < KITER; t++) {
        if (t < KITER - 1) {
            int k0 = (t + 1) * 16;
            a0 = *(const float4*)(x + (size_t)(bm + arow) * INF + k0 + acg);
            a1 = *(const float4*)(x + (size_t)(bm + arow + 64) * INF + k0 + acg);
#pragma unroll
            for (int p = 0; p < 8; p++)
                bpre[p] = W1g[(size_t)(sc0 + 16 * p) * INF + k0 + sk];
        }

        {
            float2 (*As)[130] = Asd[cb];
            float  (*Bb)[132] = Bs[cb];
#pragma unroll
            for (int kk = 0; kk < 16; kk++) {
                float4 bv0 = *(const float4*)&Bb[kk][4 * tx];
                float4 bv1 = *(const float4*)&Bb[kk][4 * tx + 64];
                u64 b00 = ((const u64*)&bv0)[0], b01 = ((const u64*)&bv0)[1];
                u64 b10 = ((const u64*)&bv1)[0], b11 = ((const u64*)&bv1)[1];
#pragma unroll
                for (int p = 0; p < 4; p++) {
                    float4 av = *(const float4*)&As[kk][ty * 8 + 2 * p];
                    u64 alo = ((const u64*)&av)[0];
                    u64 ahi = ((const u64*)&av)[1];
                    cp[2*p  ][0] = fma2(alo, b00, cp[2*p  ][0]);
                    cp[2*p  ][1] = fma2(alo, b01, cp[2*p  ][1]);
                    cp[2*p  ][2] = fma2(alo, b10, cp[2*p  ][2]);
                    cp[2*p  ][3] = fma2(alo, b11, cp[2*p  ][3]);
                    cp[2*p+1][0] = fma2(ahi, b00, cp[2*p+1][0]);
                    cp[2*p+1][1] = fma2(ahi, b01, cp[2*p+1][1]);
                    cp[2*p+1][2] = fma2(ahi, b10, cp[2*p+1][2]);
                    cp[2*p+1][3] = fma2(ahi, b11, cp[2*p+1][3]);
                }
            }
        }

        if (t < KITER - 1) {
            float2 (*As)[130] = Asd[cb ^ 1];
            float  (*Bb)[132] = Bs[cb ^ 1];
            As[acg + 0][arow] = make_float2(a0.x, a0.x);
            As[acg + 1][arow] = make_float2(a0.y, a0.y);
            As[acg + 2][arow] = make_float2(a0.z, a0.z);
            As[acg + 3][arow] = make_float2(a0.w, a0.w);
            As[acg + 0][arow + 64] = make_float2(a1.x, a1.x);
            As[acg + 1][arow + 64] = make_float2(a1.y, a1.y);
            As[acg + 2][arow + 64] = make_float2(a1.z, a1.z);
            As[acg + 3][arow + 64] = make_float2(a1.w, a1.w);
#pragma unroll
            for (int p = 0; p < 8; p++)
                Bb[sk][sc0 + 16 * p] = bpre[p];
            __syncthreads();
        }
        cb ^= 1;
    }

#pragma unroll
    for (int rr = 0; rr < 8; rr++) {
        int r = bm + ty * 8 + rr;
        float* orow = g_cur1 + (size_t)r * Hdim;
#pragma unroll
        for (int jj = 0; jj < 2; jj++) {
            int c = 4 * tx + 64 * jj;
            float2 v0 = unpack2(cp[rr][2 * jj]);
            float2 v1 = unpack2(cp[rr][2 * jj + 1]);
            float4 s;
            s.x = __fadd_rn(v0.x, b1s[c + 0]);
            s.y = __fadd_rn(v0.y, b1s[c + 1]);
            s.z = __fadd_rn(v1.x, b1s[c + 2]);
            s.w = __fadd_rn(v1.y, b1s[c + 3]);
            *(float4*)&orow[c] = s;
        }
    }
}

// ============================================================
// lif1: UNCHANGED. Thread = (b,h), membrane in one register, spikes via
// warp ballots (bit i of word w = h = 32w+i).
// ============================================================
__global__ __launch_bounds__(256) void lif1_kernel() {
    const int tid = blockIdx.x * 256 + threadIdx.x;   // = b*128 + h
    const float c = g_cur1[tid];
    const int b = tid >> 7;
    const int word = (tid >> 5) & 3;
    const int lane = threadIdx.x & 31;

    unsigned* dst = g_spk + (size_t)b * 4 + word;
    float m = 0.0f;
#pragma unroll
    for (int t = 0; t < NSTEP; t++) {
        float mo = m;
        m = __fmaf_rn(0.9f, mo, c);
        if (mo > 1.0f) m = __fadd_rn(m, -1.0f);
        unsigned msk = __ballot_sync(0xffffffffu, m > 1.0f);
        if (lane == 0) dst[(size_t)t * Bsz * 4] = msk;
    }
}

// ============================================================
// cur2: cur2[item] = spikes(item) @ W2q^T + b2, item = (t,b,q).
// R16: 4 work items per thread (stride K = total/4, K even -> parity q
// and thus the smem weight base are CONSTANT per thread), amortizing the
// per-block W2-repack prologue 4x and prefetching all 4 masks up front.
// Per-item accumulation chain is bitwise identical (ascending-h
// predicated add.rn.f32x2; +b2 post-reduction) -> rel_err stays 0.0.
// ============================================================
#define CUR2_ITEMS   ((size_t)NSTEP * Bsz * 2)   // 1,638,400
#define CUR2_PER_THD 4
#define CUR2_STRIDE  (CUR2_ITEMS / CUR2_PER_THD) // 409,600 (even)

__global__ __launch_bounds__(256) void cur2_kernel(const float* __restrict__ W2g,
                                                   const float* __restrict__ b2g) {
    __shared__ u64 w2q[2][Hdim][4];   // 8 KB: [parity][h][pairs]

    const int tid = threadIdx.x;
    {   // repack: exactly 256 entries = 256 threads
        int qq = tid >> 7;
        int h  = tid & 127;
        int o0 = qq * 5;
        w2q[qq][h][0] = pack2(W2g[(o0 + 0) * Hdim + h], W2g[(o0 + 1) * Hdim + h]);
        w2q[qq][h][1] = pack2(W2g[(o0 + 2) * Hdim + h], W2g[(o0 + 3) * Hdim + h]);
        w2q[qq][h][2] = pack2(W2g[(o0 + 4) * Hdim + h], 0.0f);
        w2q[qq][h][3] = 0ull;
    }
    __syncthreads();

    const size_t gid0 = (size_t)blockIdx.x * 256 + tid;   // item index, k=0
    const int q = (int)(gid0 & 1);                        // same for all 4 items

    u64 b2p0 = pack2(b2g[q * 5 + 0], b2g[q * 5 + 1]);
    u64 b2p1 = pack2(b2g[q * 5 + 2], b2g[q * 5 + 3]);
    u64 b2p2 = pack2(b2g[q * 5 + 4], 0.0f);

    const u64* wbase = &w2q[q][0][0];
    const u64 ONE2 = 0x3F8000003F800000ull;

    // prefetch all 4 masks (independent LDG.128s, latency overlapped)
    uint4 mks[CUR2_PER_THD];
#pragma unroll
    for (int k = 0; k < CUR2_PER_THD; k++) {
        size_t gid = gid0 + (size_t)k * CUR2_STRIDE;
        mks[k] = *(const uint4*)(g_spk + (gid >> 1) * 4);
    }

#pragma unroll
    for (int k = 0; k < CUR2_PER_THD; k++) {
        uint4 mk = mks[k];
        u64 a0 = 0ull, a1 = 0ull, a2 = 0ull;

#pragma unroll
        for (int w = 0; w < 4; w++) {
            unsigned mw = (w == 0) ? mk.x : (w == 1) ? mk.y : (w == 2) ? mk.z : mk.w;
            const u64* wp = wbase + (w * 32) * 4;
#pragma unroll 8
            for (int bit = 0; bit < 32; bit++) {
                unsigned tst = mw & (1u << bit);
                u64 w0 = wp[0], w1 = wp[1], w2 = wp[2];
                asm("{\n\t"
                    ".reg .pred p;\n\t"
                    "setp.ne.u32 p, %6, 0;\n\t"
                    "@p add.rn.f32x2 %0, %0, %3;\n\t"
                    "@p add.rn.f32x2 %1, %1, %4;\n\t"
                    "@p add.rn.f32x2 %2, %2, %5;\n\t"
                    "}"
                    : "+l"(a0), "+l"(a1), "+l"(a2)
                    : "l"(w0), "l"(w1), "l"(w2), "r"(tst));
                wp += 4;
            }
        }

        // +b2 after the full reduction (element-wise fadd_rn)
        size_t gid = gid0 + (size_t)k * CUR2_STRIDE;
        u64* dst = g_cur2 + gid * 3;
        dst[0] = fma2(ONE2, a0, b2p0);
        dst[1] = fma2(ONE2, a1, b2p1);
        dst[2] = fma2(ONE2, a2, b2p2);
    }
}

// ============================================================
// scan: UNCHANGED. 25-step layer-2 LIF over precomputed cur2.
// ============================================================
__global__ __launch_bounds__(128) void scan_kernel(float* __restrict__ out) {
    const int sid = blockIdx.x * 128 + threadIdx.x;   // = b*2 + q
    const int q = sid & 1;
    const int b = sid >> 1;

    float m2a = 0.0f, m2b = 0.0f, m2c = 0.0f, m2d = 0.0f, m2e = 0.0f;
    float* outp = out + (size_t)b * OUTD + q * 5;

    const u64* src0 = g_cur2 + (size_t)sid * 3;
    u64 c0 = src0[0], c1 = src0[1], c2 = src0[2];

#pragma unroll 1
    for (int t = 0; t < NSTEP; t++) {
        u64 n0 = c0, n1 = c1, n2 = c2;
        if (t < NSTEP - 1) {
            const u64* srcn = g_cur2 + ((size_t)(t + 1) * Bsz * 2 + sid) * 3;
            n0 = srcn[0]; n1 = srcn[1]; n2 = srcn[2];
        }

        float2 c01 = unpack2(c0);
        float2 c23 = unpack2(c1);
        float2 c4x = unpack2(c2);

        float* op = outp + (size_t)t * Bsz * OUTD;
        {
            float mo = m2a;
            float m = __fmaf_rn(0.9f, mo, c01.x);
            if (mo > 1.0f) m = __fadd_rn(m, -1.0f);
            m2a = m; op[0] = (m > 1.0f) ? 1.0f : 0.0f;
        }
        {
            float mo = m2b;
            float m = __fmaf_rn(0.9f, mo, c01.y);
            if (mo > 1.0f) m = __fadd_rn(m, -1.0f);
            m2b = m; op[1] = (m > 1.0f) ? 1.0f : 0.0f;
        }
        {
            float mo = m2c;
            float m = __fmaf_rn(0.9f, mo, c23.x);
            if (mo > 1.0f) m = __fadd_rn(m, -1.0f);
            m2c = m; op[2] = (m > 1.0f) ? 1.0f : 0.0f;
        }
        {
            float mo = m2d;
            float m = __fmaf_rn(0.9f, mo, c23.y);
            if (mo > 1.0f) m = __fadd_rn(m, -1.0f);
            m2d = m; op[3] = (m > 1.0f) ? 1.0f : 0.0f;
        }
        {
            float mo = m2e;
            float m = __fmaf_rn(0.9f, mo, c4x.x);
            if (mo > 1.0f) m = __fadd_rn(m, -1.0f);
            m2e = m; op[4] = (m > 1.0f) ? 1.0f : 0.0f;
        }

        c0 = n0; c1 = n1; c2 = n2;
    }
}

// ============================================================
extern "C" void kernel_launch(void* const* d_in, const int* in_sizes, int n_in,
                              void* d_out, int out_size) {
    (void)in_sizes; (void)n_in; (void)out_size;
    const float* x  = (const float*)d_in[0];
    const float* W1 = (const float*)d_in[1];
    const float* b1 = (const float*)d_in[2];
    const float* W2 = (const float*)d_in[3];
    const float* b2 = (const float*)d_in[4];
    float* out = (float*)d_out;

    gemm1_kernel<<<Bsz / 128, 256>>>(x, W1, b1);
    lif1_kernel<<<(Bsz * Hdim) / 256, 256>>>();
    cur2_kernel<<<(unsigned)(CUR2_STRIDE / 256), 256>>>(W2, b2);
    scan_kernel<<<(Bsz * 2) / 128, 128>>>(out);
}

// round 17
// speedup vs baseline: 1.8310x; 1.8310x over previous
#include <cuda_runtime.h>
#include <cuda_bf16.h>

// Problem constants (fixed by the dataset)
#define Bsz   32768
#define INF   784
#define Hdim  128
#define OUTD  10
#define NSTEP 25

typedef unsigned long long u64;

// -------- packed f32x2 helpers (Blackwell dual-fp32 pipe) --------
__device__ __forceinline__ u64 fma2(u64 a, u64 b, u64 c) {
    u64 d;
    asm("fma.rn.f32x2 %0, %1, %2, %3;" : "=l"(d) : "l"(a), "l"(b), "l"(c));
    return d;
}
__device__ __forceinline__ u64 pack2(float x, float y) {
    u64 d;
    asm("mov.b64 %0, {%1, %2};" : "=l"(d) : "f"(x), "f"(y));
    return d;
}
__device__ __forceinline__ float2 unpack2(u64 a) {
    float2 r;
    asm("mov.b64 {%0, %1}, %2;" : "=f"(r.x), "=f"(r.y) : "l"(a));
    return r;
}

// -------- device scratch (no allocation allowed) --------
__device__ float    g_cur1[(size_t)Bsz * Hdim];              // 16 MB
__device__ unsigned g_spk[(size_t)NSTEP * Bsz * 4];          // 13.1 MB spike bitmasks
__device__ u64      g_cur2[(size_t)NSTEP * Bsz * 6];         // 78.6 MB cur2 (5 pairs + pad)

// ============================================================
// gemm1: UNCHANGED (R15). At the dual-fp32 FMA roofline (~174us):
// fma pipe counter 47.6% == one FFMA2 per 2cyc == saturated.
// ============================================================
__global__ __launch_bounds__(256, 2) void gemm1_kernel(const float* __restrict__ x,
                                                       const float* __restrict__ W1g,
                                                       const float* __restrict__ b1) {
    __shared__ __align__(16) float2 Asd[2][16][130];
    __shared__ __align__(16) float  Bs[2][16][132];
    __shared__ float  b1s[128];

    const int tid = threadIdx.x;
    const int bm = blockIdx.x * 128;

    if (tid < 128) b1s[tid] = b1[tid];

    const int arow = tid >> 2;
    const int acg  = (tid & 3) * 4;
    const int sk  = tid & 15;
    const int sc0 = tid >> 4;

    const int tx = tid & 15;
    const int ty = tid >> 4;

    u64 cp[8][4];
#pragma unroll
    for (int rr = 0; rr < 8; rr++)
#pragma unroll
        for (int j = 0; j < 4; j++) cp[rr][j] = 0ull;

    float4 a0 = *(const float4*)(x + (size_t)(bm + arow) * INF + acg);
    float4 a1 = *(const float4*)(x + (size_t)(bm + arow + 64) * INF + acg);
    float bpre[8];
#pragma unroll
    for (int p = 0; p < 8; p++)
        bpre[p] = W1g[(size_t)(sc0 + 16 * p) * INF + sk];

    {
        float2 (*As)[130] = Asd[0];
        float  (*Bb)[132] = Bs[0];
        As[acg + 0][arow] = make_float2(a0.x, a0.x);
        As[acg + 1][arow] = make_float2(a0.y, a0.y);
        As[acg + 2][arow] = make_float2(a0.z, a0.z);
        As[acg + 3][arow] = make_float2(a0.w, a0.w);
        As[acg + 0][arow + 64] = make_float2(a1.x, a1.x);
        As[acg + 1][arow + 64] = make_float2(a1.y, a1.y);
        As[acg + 2][arow + 64] = make_float2(a1.z, a1.z);
        As[acg + 3][arow + 64] = make_float2(a1.w, a1.w);
#pragma unroll
        for (int p = 0; p < 8; p++)
            Bb[sk][sc0 + 16 * p] = bpre[p];
    }
    __syncthreads();

    const int KITER = INF / 16;  // 49
    int cb = 0;
    for (int t = 0; t < KITER; t++) {
        if (t < KITER - 1) {
            int k0 = (t + 1) * 16;
            a0 = *(const float4*)(x + (size_t)(bm + arow) * INF + k0 + acg);
            a1 = *(const float4*)(x + (size_t)(bm + arow + 64) * INF + k0 + acg);
#pragma unroll
            for (int p = 0; p < 8; p++)
                bpre[p] = W1g[(size_t)(sc0 + 16 * p) * INF + k0 + sk];
        }

        {
            float2 (*As)[130] = Asd[cb];
            float  (*Bb)[132] = Bs[cb];
#pragma unroll
            for (int kk = 0; kk < 16; kk++) {
                float4 bv0 = *(const float4*)&Bb[kk][4 * tx];
                float4 bv1 = *(const float4*)&Bb[kk][4 * tx + 64];
                u64 b00 = ((const u64*)&bv0)[0], b01 = ((const u64*)&bv0)[1];
                u64 b10 = ((const u64*)&bv1)[0], b11 = ((const u64*)&bv1)[1];
#pragma unroll
                for (int p = 0; p < 4; p++) {
                    float4 av = *(const float4*)&As[kk][ty * 8 + 2 * p];
                    u64 alo = ((const u64*)&av)[0];
                    u64 ahi = ((const u64*)&av)[1];
                    cp[2*p  ][0] = fma2(alo, b00, cp[2*p  ][0]);
                    cp[2*p  ][1] = fma2(alo, b01, cp[2*p  ][1]);
                    cp[2*p  ][2] = fma2(alo, b10, cp[2*p  ][2]);
                    cp[2*p  ][3] = fma2(alo, b11, cp[2*p  ][3]);
                    cp[2*p+1][0] = fma2(ahi, b00, cp[2*p+1][0]);
                    cp[2*p+1][1] = fma2(ahi, b01, cp[2*p+1][1]);
                    cp[2*p+1][2] = fma2(ahi, b10, cp[2*p+1][2]);
                    cp[2*p+1][3] = fma2(ahi, b11, cp[2*p+1][3]);
                }
            }
        }

        if (t < KITER - 1) {
            float2 (*As)[130] = Asd[cb ^ 1];
            float  (*Bb)[132] = Bs[cb ^ 1];
            As[acg + 0][arow] = make_float2(a0.x, a0.x);
            As[acg + 1][arow] = make_float2(a0.y, a0.y);
            As[acg + 2][arow] = make_float2(a0.z, a0.z);
            As[acg + 3][arow] = make_float2(a0.w, a0.w);
            As[acg + 0][arow + 64] = make_float2(a1.x, a1.x);
            As[acg + 1][arow + 64] = make_float2(a1.y, a1.y);
            As[acg + 2][arow + 64] = make_float2(a1.z, a1.z);
            As[acg + 3][arow + 64] = make_float2(a1.w, a1.w);
#pragma unroll
            for (int p = 0; p < 8; p++)
                Bb[sk][sc0 + 16 * p] = bpre[p];
            __syncthreads();
        }
        cb ^= 1;
    }

#pragma unroll
    for (int rr = 0; rr < 8; rr++) {
        int r = bm + ty * 8 + rr;
        float* orow = g_cur1 + (size_t)r * Hdim;
#pragma unroll
        for (int jj = 0; jj < 2; jj++) {
            int c = 4 * tx + 64 * jj;
            float2 v0 = unpack2(cp[rr][2 * jj]);
            float2 v1 = unpack2(cp[rr][2 * jj + 1]);
            float4 s;
            s.x = __fadd_rn(v0.x, b1s[c + 0]);
            s.y = __fadd_rn(v0.y, b1s[c + 1]);
            s.z = __fadd_rn(v1.x, b1s[c + 2]);
            s.w = __fadd_rn(v1.y, b1s[c + 3]);
            *(float4*)&orow[c] = s;
        }
    }
}

// ============================================================
// lif1: UNCHANGED. Thread = (b,h), membrane in one register, spikes via
// warp ballots (bit i of word w = h = 32w+i).
// ============================================================
__global__ __launch_bounds__(256) void lif1_kernel() {
    const int tid = blockIdx.x * 256 + threadIdx.x;   // = b*128 + h
    const float c = g_cur1[tid];
    const int b = tid >> 7;
    const int word = (tid >> 5) & 3;
    const int lane = threadIdx.x & 31;

    unsigned* dst = g_spk + (size_t)b * 4 + word;
    float m = 0.0f;
#pragma unroll
    for (int t = 0; t < NSTEP; t++) {
        float mo = m;
        m = __fmaf_rn(0.9f, mo, c);
        if (mo > 1.0f) m = __fadd_rn(m, -1.0f);
        unsigned msk = __ballot_sync(0xffffffffu, m > 1.0f);
        if (lane == 0) dst[(size_t)t * Bsz * 4] = msk;
    }
}

// ============================================================
// cur2: cur2[t,b] = spikes(t,b) @ W2^T + b2.
// R17: ONE thread per (t,b) item computing ALL 10 outputs (was 2 threads
// x 5 outputs): per bit = LOP3.pred + 3 LDS (2xLDS.128+LDS.64 from a
// 48B-aligned row) + 5 predicated add.rn.f32x2 -> LDS per output-bit
// drops 0.4 -> 0.3 and total warp-issues drop ~1.35x. Single 128-bit
// loop body (I$-L0 safe, unlike the R16 4x-unroll).
// Accumulation chains bitwise identical: each packed pair is an exact
// ascending-h predicated add chain (@!p no-op; @p add.rn == fma2(1,w,acc));
// +b2 post-reduction via fma2(ONE2,acc,b2) == element-wise fadd_rn.
// ============================================================
__global__ __launch_bounds__(256) void cur2_kernel(const float* __restrict__ W2g,
                                                   const float* __restrict__ b2g) {
    __shared__ __align__(16) u64 w2s[Hdim][6];   // 6 KB: [h][pair0..4, pad]

    const int tid = threadIdx.x;
    // repack: 640 entries, 256 threads
    for (int i = tid; i < Hdim * 5; i += 256) {
        int h = i / 5, p = i - 5 * h;
        w2s[h][p] = pack2(W2g[(2 * p) * Hdim + h], W2g[(2 * p + 1) * Hdim + h]);
    }
    __syncthreads();

    const size_t gid = (size_t)blockIdx.x * 256 + tid;   // = t*Bsz + b
    uint4 mk = *(const uint4*)(g_spk + gid * 4);

    u64 b2p0 = *(const u64*)(b2g + 0);
    u64 b2p1 = *(const u64*)(b2g + 2);
    u64 b2p2 = *(const u64*)(b2g + 4);
    u64 b2p3 = *(const u64*)(b2g + 6);
    u64 b2p4 = *(const u64*)(b2g + 8);

    u64 a0 = 0ull, a1 = 0ull, a2 = 0ull, a3 = 0ull, a4 = 0ull;

#pragma unroll
    for (int w = 0; w < 4; w++) {
        unsigned mw = (w == 0) ? mk.x : (w == 1) ? mk.y : (w == 2) ? mk.z : mk.w;
        const u64* wp = &w2s[w * 32][0];
#pragma unroll 8
        for (int bit = 0; bit < 32; bit++) {
            unsigned tst = mw & (1u << bit);
            u64 w0 = wp[0], w1 = wp[1], w2 = wp[2], w3 = wp[3], w4 = wp[4];
            asm("{\n\t"
                ".reg .pred p;\n\t"
                "setp.ne.u32 p, %10, 0;\n\t"
                "@p add.rn.f32x2 %0, %0, %5;\n\t"
                "@p add.rn.f32x2 %1, %1, %6;\n\t"
                "@p add.rn.f32x2 %2, %2, %7;\n\t"
                "@p add.rn.f32x2 %3, %3, %8;\n\t"
                "@p add.rn.f32x2 %4, %4, %9;\n\t"
                "}"
                : "+l"(a0), "+l"(a1), "+l"(a2), "+l"(a3), "+l"(a4)
                : "l"(w0), "l"(w1), "l"(w2), "l"(w3), "l"(w4), "r"(tst));
            wp += 6;
        }
    }

    // +b2 after the full reduction (element-wise fadd_rn)
    const u64 ONE2 = 0x3F8000003F800000ull;
    u64* dst = g_cur2 + gid * 6;
    dst[0] = fma2(ONE2, a0, b2p0);
    dst[1] = fma2(ONE2, a1, b2p1);
    dst[2] = fma2(ONE2, a2, b2p2);
    dst[3] = fma2(ONE2, a3, b2p3);
    dst[4] = fma2(ONE2, a4, b2p4);
}

// ============================================================
// scan: 25-step layer-2 LIF over precomputed cur2. Thread = b (all 10
// outputs); next-step cur2 prefetched; scalar op sequence unchanged
// (exact FFMA + predicated-subtract model -> bitwise identical).
// ============================================================
__global__ __launch_bounds__(256) void scan_kernel(float* __restrict__ out) {
    const int b = blockIdx.x * 256 + threadIdx.x;

    float m2[OUTD];
#pragma unroll
    for (int o = 0; o < OUTD; o++) m2[o] = 0.0f;

    float* outp = out + (size_t)b * OUTD;

    const u64* src0 = g_cur2 + (size_t)b * 6;
    u64 c[5], n[5];
#pragma unroll
    for (int p = 0; p < 5; p++) c[p] = src0[p];

#pragma unroll 1
    for (int t = 0; t < NSTEP; t++) {
#pragma unroll
        for (int p = 0; p < 5; p++) n[p] = c[p];
        if (t < NSTEP - 1) {
            const u64* srcn = g_cur2 + ((size_t)(t + 1) * Bsz + b) * 6;
#pragma unroll
            for (int p = 0; p < 5; p++) n[p] = srcn[p];
        }

        float* op = outp + (size_t)t * Bsz * OUTD;
#pragma unroll
        for (int p = 0; p < 5; p++) {
            float2 cv = unpack2(c[p]);
            float so0, so1;
            {
                float mo = m2[2 * p];
                float m = __fmaf_rn(0.9f, mo, cv.x);
                if (mo > 1.0f) m = __fadd_rn(m, -1.0f);
                m2[2 * p] = m;
                so0 = (m > 1.0f) ? 1.0f : 0.0f;
            }
            {
                float mo = m2[2 * p + 1];
                float m = __fmaf_rn(0.9f, mo, cv.y);
                if (mo > 1.0f) m = __fadd_rn(m, -1.0f);
                m2[2 * p + 1] = m;
                so1 = (m > 1.0f) ? 1.0f : 0.0f;
            }
            *(float2*)(op + 2 * p) = make_float2(so0, so1);
        }

#pragma unroll
        for (int p = 0; p < 5; p++) c[p] = n[p];
    }
}

// ============================================================
extern "C" void kernel_launch(void* const* d_in, const int* in_sizes, int n_in,
                              void* d_out, int out_size) {
    (void)in_sizes; (void)n_in; (void)out_size;
    const float* x  = (const float*)d_in[0];
    const float* W1 = (const float*)d_in[1];
    const float* b1 = (const float*)d_in[2];
    const float* W2 = (const float*)d_in[3];
    const float* b2 = (const float*)d_in[4];
    float* out = (float*)d_out;

    gemm1_kernel<<<Bsz / 128, 256>>>(x, W1, b1);
    lif1_kernel<<<(Bsz * Hdim) / 256, 256>>>();
    cur2_kernel<<<(NSTEP * Bsz) / 256, 256>>>(W2, b2);
    scan_kernel<<<Bsz / 256, 256>>>(out);
}